// round 9
// baseline (speedup 1.0000x reference)
#include <cuda_runtime.h>
#include <cuda_bf16.h>
#include <cstddef>

// B=32, H=W=64, C=64, K=3, S=1, PAD=1; Hp=Wp=66, OUT=192. Pure gather:
//   out[b,c2,r,s] = up_flat[c2*4356 + ip*66 + jp], ip=r/3+r%3, jp=s/3+s%3
//   up_flat[t]: p=t>>6, c=t&63, rp=p/66, cp=p%66;
//   interior -> in[b, (p-2rp-65), c] else 0.
// Store-side: thread tx writes cols 4tx..4tx+3 (coalesced float4). With
// j=tx/3, m=tx%3 its sources all lie in src[4j..4j+5]:
//   m=0:(a0,a1,a2,a1)  m=1:(a2,a3,a2,a3)  m=2:(a4,a3,a4,a5)
// -> one LDS.128 + one LDS.64 per quad (3-lane broadcast), vs 4 scalar LDS.
#define HP      66
#define HPP     68               // padded row stride: 16B-aligned 4j offsets
#define NP      (HP * HP)        // 4356
#define OUT     192
#define BATCH   32

__global__ __launch_bounds__(384)
void padding_jacobians_kernel(const float* __restrict__ in,
                              float* __restrict__ out) {
    __shared__ float sm[HP * HPP];         // 17952 B

    const unsigned c2 = blockIdx.x;        // 0..63
    const unsigned b  = blockIdx.y;        // 0..31
    const int tx  = threadIdx.x;           // 0..47 (output quad)
    const int ty  = threadIdx.y;           // 0..7
    const int tid = ty * 48 + tx;

    const float* __restrict__ inb = in + (size_t)b * (64 * 64 * 64);
    const unsigned base_t = c2 * NP;       // multiple of 4

    // ---- Load phase: padded 66x66 window into 66x68 smem, float2 granules
    // (t even => c even, never crosses a p boundary since 2|64). 2178 float2s.
    #pragma unroll 1
    for (unsigned idx = tid; idx < NP / 2; idx += 384) {
        unsigned i   = 2u * idx;                 // window offset (even)
        unsigned row = (i * 993u) >> 16;         // == i/66 (exact, i<4356)
        unsigned col = i - 66u * row;
        unsigned t   = base_t + i;
        unsigned p   = t >> 6;
        unsigned c   = t & 63u;
        unsigned rp  = (p * 993u) >> 16;         // == p/66
        unsigned cp  = p - 66u * rp;
        float2 v = make_float2(0.f, 0.f);
        if ((rp - 1u) < 64u && (cp - 1u) < 64u) {
            v = __ldcs(reinterpret_cast<const float2*>(
                    inb + ((p - 2u * rp - 65u) << 6) + c));   // read-once
        }
        *reinterpret_cast<float2*>(sm + row * HPP + col) = v;  // even: aligned
    }
    __syncthreads();

    // ---- Store phase: lane tx -> cols 4tx..4tx+3, rows r = ty + 8*it.
    const int j = tx / 3;                    // 0..15 (3 lanes share window)
    const int m = tx - 3 * j;                // 0,1,2

    float* __restrict__ outp =
        out + (size_t)(b * 64 + c2) * (OUT * OUT) + (size_t)ty * OUT + 4 * tx;

    // maintain o=r/3, k=r%3 as r steps by 8: k'=(k+2)%3; o += (k==0)?2:3
    int o = ty / 3;
    int k = ty % 3;
    #pragma unroll 4
    for (int it = 0; it < OUT / 8; ++it) {
        const float* src = sm + (o + k) * HPP + 4 * j;   // 16B aligned
        float4 a  = *reinterpret_cast<const float4*>(src);      // a0..a3
        float2 b2 = *reinterpret_cast<const float2*>(src + 4);  // a4,a5
        float4 v;
        if (m == 0)      v = make_float4(a.x,  a.y, a.z,  a.y);
        else if (m == 1) v = make_float4(a.z,  a.w, a.z,  a.w);
        else             v = make_float4(b2.x, a.w, b2.x, b2.y);
        __stcs(reinterpret_cast<float4*>(outp), v);   // write-once stream
        outp += (size_t)8 * OUT;
        o += (k == 0) ? 2 : 3;
        k = (k == 2) ? 1 : ((k == 1) ? 0 : 2);        // (k+2)%3
    }
}

extern "C" void kernel_launch(void* const* d_in, const int* in_sizes, int n_in,
                              void* d_out, int out_size) {
    const float* in  = (const float*)d_in[0];
    float*       out = (float*)d_out;
    (void)in_sizes; (void)n_in; (void)out_size;

    dim3 grid(64, BATCH);     // (c2, b)
    dim3 block(48, 8);        // 384 threads
    padding_jacobians_kernel<<<grid, block>>>(in, out);
}

// round 10
// speedup vs baseline: 1.1311x; 1.1311x over previous
#include <cuda_runtime.h>
#include <cuda_bf16.h>
#include <cstddef>

// B=32, H=W=64, C=64, K=3, S=1, PAD=1; Hp=Wp=66, OUT=192. Pure gather:
//   out[b,c2,r,s] = up_flat[c2*4356 + ip*66 + jp], ip=r/3+r%3, jp=s/3+s%3
//   up_flat[t]: p=t>>6, c=t&63, rp=p/66, cp=p%66;
//   interior -> in[b, (p-2rp-65), c] else 0.
// Row multiplicity: out row r depends only on ip(r); for window row ip the
// output rows are {3ip, 3ip-2, 3ip-4} ∩ [0,192). Build each float4 once,
// store 2-3 times -> ~2.7x fewer shared loads, same store bytes.
#define HP      66
#define NP      (HP * HP)        // 4356 floats per (b,c2) window
#define OUT     192
#define BATCH   32

__global__ __launch_bounds__(384)
void padding_jacobians_kernel(const float* __restrict__ in,
                              float* __restrict__ out) {
    __shared__ float sm[NP];               // 17424 B

    const unsigned c2 = blockIdx.x;        // 0..63
    const unsigned b  = blockIdx.y;        // 0..31
    const int tx  = threadIdx.x;           // 0..47  (s-quad index)
    const int ty  = threadIdx.y;           // 0..7
    const int tid = ty * 48 + tx;

    const float* __restrict__ inb = in + (size_t)b * (64 * 64 * 64);
    const unsigned base_t = c2 * NP;       // multiple of 4

    // ---- Load phase: sm[i] = up_flat[base_t + i] (zero on padded border).
    // float4 granules never cross a p boundary (t%4==0, 4|64). 1089 float4s.
    #pragma unroll 1
    for (unsigned q = tid; q < NP / 4; q += 384) {
        unsigned t  = base_t + 4u * q;
        unsigned p  = t >> 6;
        unsigned c  = t & 63u;
        unsigned rp = (p * 993u) >> 16;    // == p/66 for p < 4356 (exact)
        unsigned cp = p - 66u * rp;
        float4 v = make_float4(0.f, 0.f, 0.f, 0.f);
        if ((rp - 1u) < 64u && (cp - 1u) < 64u) {
            v = __ldcs(reinterpret_cast<const float4*>(
                    inb + ((p - 2u * rp - 65u) << 6) + c));   // read-once
        }
        reinterpret_cast<float4*>(sm)[q] = v;
    }
    __syncthreads();

    // ---- Store phase: iterate window rows ip = ty + 8*it (0..65).
    // Thread gathers its 4 values once, stores to every r with ip(r)=ip.
    const int s0 = 4 * tx;
    const int jp0 =  s0      / 3 +  s0      % 3;
    const int jp1 = (s0 + 1) / 3 + (s0 + 1) % 3;
    const int jp2 = (s0 + 2) / 3 + (s0 + 2) % 3;
    const int jp3 = (s0 + 3) / 3 + (s0 + 3) % 3;

    float* __restrict__ outbase =
        out + (size_t)(b * 64 + c2) * (OUT * OUT) + s0;

    #pragma unroll
    for (int it = 0; it < 9; ++it) {
        const int ip = ty + 8 * it;
        if (ip < 66) {
            const float* row = sm + ip * HP;
            float4 v = make_float4(row[jp0], row[jp1], row[jp2], row[jp3]);
            const int r0 = 3 * ip;         // candidates r0, r0-2, r0-4
            if (r0 < OUT)
                __stcs(reinterpret_cast<float4*>(outbase + (size_t)r0 * OUT), v);
            if ((unsigned)(r0 - 2) < OUT)
                __stcs(reinterpret_cast<float4*>(outbase + (size_t)(r0 - 2) * OUT), v);
            if ((unsigned)(r0 - 4) < OUT)
                __stcs(reinterpret_cast<float4*>(outbase + (size_t)(r0 - 4) * OUT), v);
        }
    }
}

extern "C" void kernel_launch(void* const* d_in, const int* in_sizes, int n_in,
                              void* d_out, int out_size) {
    const float* in  = (const float*)d_in[0];
    float*       out = (float*)d_out;
    (void)in_sizes; (void)n_in; (void)out_size;

    dim3 grid(64, BATCH);     // (c2, b)
    dim3 block(48, 8);        // 384 threads
    padding_jacobians_kernel<<<grid, block>>>(in, out);
}